// round 2
// baseline (speedup 1.0000x reference)
#include <cuda_runtime.h>

// Problem constants (match reference)
#define BATCH   512
#define IN_DIM  784
#define OUT_DIM 10
#define STEPS   200
#define NSCAN   (STEPS - 1)   // 199 drive slices / scan steps

// LIF constants
#define A_M     0.995f        // 1 - DT/TAU_M
#define G_M     0.005f        // DT/TAU_M
#define A_S     0.98f         // 1 - DT/TAU_S

__global__ __launch_bounds__(256, 4)
void snn_kernel(const float* __restrict__ x,     // [B, IN, STEPS]
                const float* __restrict__ w,     // [O, IN]
                float* __restrict__ out)         // [B, O]
{
    __shared__ float wsh[IN_DIM * OUT_DIM];      // [i][o] layout, 31360 B
    __shared__ float drv[NSCAN * OUT_DIM];       // [t][o], 7960 B

    const int b   = blockIdx.x;
    const int tid = threadIdx.x;

    // Load weights into smem transposed: wsh[i*10 + o] = w[o*784 + i]
    for (int k = tid; k < IN_DIM * OUT_DIM; k += blockDim.x) {
        int i = k / OUT_DIM;
        int o = k - i * OUT_DIM;
        wsh[k] = w[o * IN_DIM + i];
    }
    __syncthreads();

    const float* xb = x + (size_t)b * IN_DIM * STEPS;

    // Each thread t in [0, 199) computes drive[t][0..9] = sum_i x[b,i,t]*w[o,i]
    if (tid < NSCAN) {
        const int t = tid;
        float acc[OUT_DIM];
        #pragma unroll
        for (int o = 0; o < OUT_DIM; o++) acc[o] = 0.0f;

        // i-loop unrolled by 8 for memory-level parallelism.
        // Loads are coalesced across the warp (consecutive t -> consecutive addr).
        #pragma unroll 1
        for (int i0 = 0; i0 < IN_DIM; i0 += 8) {
            float v[8];
            #pragma unroll
            for (int j = 0; j < 8; j++)
                v[j] = xb[(size_t)(i0 + j) * STEPS + t];
            #pragma unroll
            for (int j = 0; j < 8; j++) {
                if (v[j] != 0.0f) {  // ~2% dense: skip the 10 FMAs most of the time
                    const float* wr = &wsh[(i0 + j) * OUT_DIM];
                    #pragma unroll
                    for (int o = 0; o < OUT_DIM; o++)
                        acc[o] = fmaf(v[j], wr[o], acc[o]);
                }
            }
        }
        #pragma unroll
        for (int o = 0; o < OUT_DIM; o++)
            drv[t * OUT_DIM + o] = acc[o];
    }
    __syncthreads();

    // Sequential LIF scan per output neuron; record first spike time.
    if (tid < OUT_DIM) {
        const int o = tid;
        float V = 0.0f, I = 0.0f;
        int fst = 0;
        for (int t = 0; t < NSCAN; t++) {
            float Vn = A_M * V + G_M * I;
            float In = A_S * I + drv[t * OUT_DIM + o];
            if (Vn > 1.0f) { fst = t + 1; break; }  // first spike -> done
            V = Vn;
            I = In;
        }
        out[b * OUT_DIM + o] = (fst == 0) ? (float)(STEPS - 1) : (float)fst;
    }
}

extern "C" void kernel_launch(void* const* d_in, const int* in_sizes, int n_in,
                              void* d_out, int out_size)
{
    const float* x = (const float*)d_in[0];   // [512, 784, 200]
    const float* w = (const float*)d_in[1];   // [10, 784]
    float* out = (float*)d_out;               // [512, 10]
    snn_kernel<<<BATCH, 256>>>(x, w, out);
}

// round 3
// speedup vs baseline: 1.5858x; 1.5858x over previous
#include <cuda_runtime.h>

// Problem constants (match reference)
#define BATCH   512
#define IN_DIM  784
#define OUT_DIM 10
#define STEPS   200
#define NSCAN   (STEPS - 1)   // 199 drive slices / scan steps
#define IHALF   (IN_DIM / 2)  // 392, divisible by 8

// LIF constants
#define A_M     0.995f        // 1 - DT/TAU_M
#define G_M     0.005f        // DT/TAU_M
#define A_S     0.98f         // 1 - DT/TAU_S

__device__ __forceinline__ float ldcs(const float* p) {
    float v;
    asm volatile("ld.global.cs.f32 %0, [%1];" : "=f"(v) : "l"(p));
    return v;
}

__global__ __launch_bounds__(512, 3)
void snn_kernel(const float* __restrict__ x,     // [B, IN, STEPS]
                const float* __restrict__ w,     // [O, IN]
                float* __restrict__ out)         // [B, O]
{
    __shared__ float wsh[IN_DIM * OUT_DIM];      // [i][o], 31360 B
    __shared__ float drv[NSCAN * OUT_DIM];       // [t][o], 7960 B

    const int b    = blockIdx.x;
    const int tid  = threadIdx.x;
    const int half = tid >> 8;                   // 0 or 1: which i-half
    const int t    = tid & 255;                  // time index within half

    // Load weights into smem transposed: wsh[i*10 + o] = w[o*784 + i]
    for (int k = tid; k < IN_DIM * OUT_DIM; k += blockDim.x) {
        int i = k / OUT_DIM;
        int o = k - i * OUT_DIM;
        wsh[k] = w[o * IN_DIM + i];
    }
    __syncthreads();

    const float* xb = x + (size_t)b * IN_DIM * STEPS;

    float acc[OUT_DIM];
    #pragma unroll
    for (int o = 0; o < OUT_DIM; o++) acc[o] = 0.0f;

    if (t < NSCAN) {
        const int ibase = half * IHALF;
        const float* xh = xb + (size_t)ibase * STEPS + t;

        // 392 i's per thread, unrolled by 8 for memory-level parallelism.
        // Loads coalesced across the warp (consecutive t -> consecutive addr).
        #pragma unroll 1
        for (int i0 = 0; i0 < IHALF; i0 += 8) {
            float v[8];
            #pragma unroll
            for (int j = 0; j < 8; j++)
                v[j] = ldcs(xh + (size_t)(i0 + j) * STEPS);
            #pragma unroll
            for (int j = 0; j < 8; j++) {
                if (v[j] != 0.0f) {  // x is binary, ~2% dense
                    const float* wr = &wsh[(ibase + i0 + j) * OUT_DIM];
                    #pragma unroll
                    for (int o = 0; o < OUT_DIM; o++)
                        acc[o] += wr[o];          // v == 1.0 exactly
                }
            }
        }
    }

    // Combine the two i-half partials through smem.
    if (half == 1 && t < NSCAN) {
        #pragma unroll
        for (int o = 0; o < OUT_DIM; o++) drv[t * OUT_DIM + o] = acc[o];
    }
    __syncthreads();
    if (half == 0 && t < NSCAN) {
        #pragma unroll
        for (int o = 0; o < OUT_DIM; o++) drv[t * OUT_DIM + o] += acc[o];
    }
    __syncthreads();

    // Sequential LIF scan per output neuron; record first spike time.
    if (tid < OUT_DIM) {
        const int o = tid;
        float V = 0.0f, I = 0.0f;
        int fst = 0;
        for (int tt = 0; tt < NSCAN; tt++) {
            float Vn = A_M * V + G_M * I;
            float In = A_S * I + drv[tt * OUT_DIM + o];
            if (Vn > 1.0f) { fst = tt + 1; break; }
            V = Vn;
            I = In;
        }
        out[b * OUT_DIM + o] = (fst == 0) ? (float)(STEPS - 1) : (float)fst;
    }
}

extern "C" void kernel_launch(void* const* d_in, const int* in_sizes, int n_in,
                              void* d_out, int out_size)
{
    const float* x = (const float*)d_in[0];   // [512, 784, 200]
    const float* w = (const float*)d_in[1];   // [10, 784]
    float* out = (float*)d_out;               // [512, 10]
    snn_kernel<<<BATCH, 512>>>(x, w, out);
}